// round 1
// baseline (speedup 1.0000x reference)
#include <cuda_runtime.h>
#include <cstdint>

#define TOK  8192      // B*S
#define AH   512       // A = H*D
#define HIDW 1024
#define SEQ  2048
#define NH   8
#define HD   64
#define KW   9

// ---------------- scratch (device globals; no allocation at launch) ----------------
__device__ float g_q  [TOK * AH];
__device__ float g_k  [TOK * AH];
__device__ float g_v  [TOK * AH];
__device__ float g_dwc[TOK * AH];
__device__ float g_ca [TOK * AH];
__device__ float g_col[TOK * AH];
__device__ float g_ckl[TOK * NH * KW];

// ---------------- fast exp on the FMA pipe (avoid MUFU throughput wall) ------------
__device__ __forceinline__ float fexp(float x) {
    float y = fmaxf(x * 1.4426950408889634f, -126.0f);
    float z = y + 12582912.0f;                 // 1.5*2^23: round-to-nearest trick
    int   ni = __float_as_int(z) - 0x4B400000; // integer part
    float n  = z - 12582912.0f;
    float f  = y - n;                          // in [-0.5, 0.5]
    float p  = 1.3333558146428443e-3f;
    p = fmaf(p, f, 9.6181291976353954e-3f);
    p = fmaf(p, f, 5.5504108664821580e-2f);
    p = fmaf(p, f, 2.4022650695910071e-1f);
    p = fmaf(p, f, 6.9314718055994531e-1f);
    p = fmaf(p, f, 1.0f);
    return p * __int_as_float(0x3F800000 + (ni << 23));
}

// ---------------- generic fp32 GEMM: C[m,n] = sum_k A[m,k]*W[n,k] + bias[n] --------
// Tiles 64x64x16, 256 threads, 4x4 register micro-tile, double-buffered LDG.
// EPI==1: multiply result elementwise by aux[m*ldaux + n] before store.
template<int EPI>
__global__ __launch_bounds__(256) void gemm64(
    const float* __restrict__ A, int lda,
    const float* __restrict__ W,          // [N, 512], row-major
    const float* __restrict__ bias,       // [N]
    const float* __restrict__ aux, int ldaux,
    float* __restrict__ C)                // [M, 512]
{
    __shared__ __align__(16) float As[16][66];
    __shared__ __align__(16) float Ws[16][66];
    const int m0 = blockIdx.y << 6;
    const int n0 = blockIdx.x << 6;
    const int t  = threadIdx.x;
    const int tx = t & 15, ty = t >> 4;
    const int lm = t >> 2;
    const int lk = (t & 3) << 2;
    const float* Ap = A + (size_t)(m0 + lm) * lda + lk;
    const float* Wp = W + (size_t)(n0 + lm) * AH  + lk;

    float c[4][4] = {};
    float4 av = *(const float4*)Ap;
    float4 wv = *(const float4*)Wp;

    for (int k0 = 0; k0 < AH; k0 += 16) {
        As[lk+0][lm] = av.x; As[lk+1][lm] = av.y; As[lk+2][lm] = av.z; As[lk+3][lm] = av.w;
        Ws[lk+0][lm] = wv.x; Ws[lk+1][lm] = wv.y; Ws[lk+2][lm] = wv.z; Ws[lk+3][lm] = wv.w;
        __syncthreads();
        if (k0 + 16 < AH) {                      // prefetch next tile (hide LDG latency)
            av = *(const float4*)(Ap + k0 + 16);
            wv = *(const float4*)(Wp + k0 + 16);
        }
        #pragma unroll
        for (int kk = 0; kk < 16; kk++) {
            float2 a0 = *(const float2*)&As[kk][ty << 2];
            float2 a1 = *(const float2*)&As[kk][(ty << 2) + 2];
            float2 b0 = *(const float2*)&Ws[kk][tx << 2];
            float2 b1 = *(const float2*)&Ws[kk][(tx << 2) + 2];
            float a[4] = {a0.x, a0.y, a1.x, a1.y};
            float b[4] = {b0.x, b0.y, b1.x, b1.y};
            #pragma unroll
            for (int i = 0; i < 4; i++)
                #pragma unroll
                for (int j = 0; j < 4; j++)
                    c[i][j] = fmaf(a[i], b[j], c[i][j]);
        }
        __syncthreads();
    }

    #pragma unroll
    for (int i = 0; i < 4; i++) {
        int m = m0 + (ty << 2) + i;
        #pragma unroll
        for (int j = 0; j < 4; j++) {
            int n = n0 + (tx << 2) + j;
            float v = c[i][j] + bias[n];
            if (EPI == 1) v *= aux[(size_t)m * ldaux + n];
            C[(size_t)m * AH + n] = v;
        }
    }
}

// ---------------- depthwise 9-tap conv along sequence ------------------------------
// hc points at hidden+512 (row stride 1024). out[tok*512 + c].
__global__ void dwconv_k(const float* __restrict__ hc, const float* __restrict__ dw,
                         float* __restrict__ o)
{
    int idx = blockIdx.x * 256 + threadIdx.x;      // TOK*512
    int tok = idx >> 9, c = idx & 511;
    int s = tok & (SEQ - 1);
    float acc = 0.f;
    #pragma unroll
    for (int k = 0; k < KW; k++) {
        int sp = s + k - 4;
        if ((unsigned)sp < (unsigned)SEQ)
            acc = fmaf(hc[(size_t)(tok + k - 4) * HIDW + c], dw[c * KW + k], acc);
    }
    o[idx] = acc;
}

// ---------------- ckl GEMM: [8192,72] = ca @ Wck^T + bck ---------------------------
__global__ __launch_bounds__(256) void ckl_gemm(
    const float* __restrict__ ca, const float* __restrict__ Wck,
    const float* __restrict__ bck, float* __restrict__ ckl)
{
    __shared__ float sca[8][AH];
    int tok0 = blockIdx.x << 3;
    for (int e = threadIdx.x; e < 8 * AH; e += 256)
        sca[e >> 9][e & 511] = ca[((size_t)tok0 << 9) + e];
    __syncthreads();
    int w = threadIdx.x >> 5, lane = threadIdx.x & 31;
    const float* srow = sca[w];
    for (int n = lane; n < NH * KW; n += 32) {
        const float* wr = Wck + (size_t)n * AH;
        float a0 = 0.f, a1 = 0.f, a2 = 0.f, a3 = 0.f;
        #pragma unroll 4
        for (int cc = 0; cc < AH; cc += 4) {
            a0 = fmaf(srow[cc + 0], wr[cc + 0], a0);
            a1 = fmaf(srow[cc + 1], wr[cc + 1], a1);
            a2 = fmaf(srow[cc + 2], wr[cc + 2], a2);
            a3 = fmaf(srow[cc + 3], wr[cc + 3], a3);
        }
        ckl[(size_t)(tok0 + w) * (NH * KW) + n] = a0 + a1 + a2 + a3 + bck[n];
    }
}

// ---------------- softmax over K=9 groups ------------------------------------------
__global__ void softmax9_k(float* __restrict__ ckl)
{
    int id = blockIdx.x * 256 + threadIdx.x;       // TOK*NH
    float* p = ckl + (size_t)id * KW;
    float v[KW];
    float mx = -1e30f;
    #pragma unroll
    for (int k = 0; k < KW; k++) { v[k] = p[k]; mx = fmaxf(mx, v[k]); }
    float s = 0.f;
    #pragma unroll
    for (int k = 0; k < KW; k++) { v[k] = fexp(v[k] - mx); s += v[k]; }
    float inv = 1.f / s;
    #pragma unroll
    for (int k = 0; k < KW; k++) p[k] = v[k] * inv;
}

// ---------------- conv_out: 9-tap window of col weighted by ckl --------------------
__global__ void convout_k(const float* __restrict__ col, const float* __restrict__ ckl,
                          float* __restrict__ out)
{
    int idx = blockIdx.x * 256 + threadIdx.x;      // TOK*512
    int tok = idx >> 9, c = idx & 511;
    int s = tok & (SEQ - 1);
    int h = c >> 6;
    const float* cw = ckl + (size_t)tok * (NH * KW) + h * KW;
    float acc = 0.f;
    #pragma unroll
    for (int k = 0; k < KW; k++) {
        int sp = s + k - 4;
        if ((unsigned)sp < (unsigned)SEQ)
            acc = fmaf(col[(size_t)(tok + k - 4) * AH + c], cw[k], acc);
    }
    out[(size_t)tok * HIDW + AH + c] = acc;
}

// ---------------- flash attention, fp32, 64x64 tiles, online softmax ---------------
#define FP 66
__global__ __launch_bounds__(256) void flash_k(
    const float* __restrict__ Q, const float* __restrict__ Kd,
    const float* __restrict__ V, float* __restrict__ out)
{
    extern __shared__ float sm[];
    float* Qs = sm;                 // [d][m], d-major
    float* Ks = sm + 64 * FP;       // [d][n]
    float* Vs = sm + 2 * 64 * FP;   // [key][d]
    float* Ps = sm + 3 * 64 * FP;   // [key][m]

    const int bh = blockIdx.y;
    const int b = bh >> 3, h = bh & 7;
    const int q0 = blockIdx.x << 6;
    const int t = threadIdx.x, tx = t & 15, ty = t >> 4;
    const size_t base = (size_t)b * SEQ * AH + h * HD;

    for (int e = t; e < 4096; e += 256) {          // Q tile, scale folded in
        int tok = e >> 6, d = e & 63;
        Qs[d * FP + tok] = Q[base + (size_t)(q0 + tok) * AH + d] * 0.125f;
    }

    float acc[4][4] = {};
    float mr[4] = {-1e30f, -1e30f, -1e30f, -1e30f};
    float lr[4] = {};
    __syncthreads();

    for (int kt = 0; kt < SEQ; kt += 64) {
        for (int e = t; e < 4096; e += 256) {
            int tok = e >> 6, d = e & 63;
            Ks[d * FP + tok] = Kd[base + (size_t)(kt + tok) * AH + d];
            Vs[tok * FP + d] = V [base + (size_t)(kt + tok) * AH + d];
        }
        __syncthreads();

        // S = Q K^T (64x64), 4x4 per thread
        float s4[4][4] = {};
        #pragma unroll 8
        for (int kk = 0; kk < 64; kk++) {
            const float* qr = Qs + kk * FP + (ty << 2);
            const float* kr = Ks + kk * FP + (tx << 2);
            float2 a0 = *(const float2*)qr, a1 = *(const float2*)(qr + 2);
            float2 b0 = *(const float2*)kr, b1 = *(const float2*)(kr + 2);
            float a[4]  = {a0.x, a0.y, a1.x, a1.y};
            float bb[4] = {b0.x, b0.y, b1.x, b1.y};
            #pragma unroll
            for (int i = 0; i < 4; i++)
                #pragma unroll
                for (int j = 0; j < 4; j++)
                    s4[i][j] = fmaf(a[i], bb[j], s4[i][j]);
        }

        // online softmax per row (row spread over 16 lanes with same ty)
        #pragma unroll
        for (int i = 0; i < 4; i++) {
            float rm = fmaxf(fmaxf(s4[i][0], s4[i][1]), fmaxf(s4[i][2], s4[i][3]));
            #pragma unroll
            for (int off = 1; off < 16; off <<= 1)
                rm = fmaxf(rm, __shfl_xor_sync(0xffffffffu, rm, off));
            float mn   = fmaxf(mr[i], rm);
            float corr = fexp(mr[i] - mn);
            mr[i] = mn;
            float rs = 0.f;
            #pragma unroll
            for (int j = 0; j < 4; j++) { s4[i][j] = fexp(s4[i][j] - mn); rs += s4[i][j]; }
            #pragma unroll
            for (int off = 1; off < 16; off <<= 1)
                rs += __shfl_xor_sync(0xffffffffu, rs, off);
            lr[i] = lr[i] * corr + rs;
            #pragma unroll
            for (int j = 0; j < 4; j++) {
                acc[i][j] *= corr;
                Ps[((tx << 2) + j) * FP + (ty << 2) + i] = s4[i][j];
            }
        }
        __syncthreads();

        // O += P V
        #pragma unroll 8
        for (int kk = 0; kk < 64; kk++) {
            const float* pr = Ps + kk * FP + (ty << 2);
            const float* vr = Vs + kk * FP + (tx << 2);
            float2 a0 = *(const float2*)pr, a1 = *(const float2*)(pr + 2);
            float2 b0 = *(const float2*)vr, b1 = *(const float2*)(vr + 2);
            float a[4]  = {a0.x, a0.y, a1.x, a1.y};
            float bb[4] = {b0.x, b0.y, b1.x, b1.y};
            #pragma unroll
            for (int i = 0; i < 4; i++)
                #pragma unroll
                for (int j = 0; j < 4; j++)
                    acc[i][j] = fmaf(a[i], bb[j], acc[i][j]);
        }
        __syncthreads();
    }

    #pragma unroll
    for (int i = 0; i < 4; i++) {
        float inv = 1.f / lr[i];
        float4 o;
        o.x = acc[i][0] * inv; o.y = acc[i][1] * inv;
        o.z = acc[i][2] * inv; o.w = acc[i][3] * inv;
        *(float4*)&out[(size_t)(b * SEQ + q0 + (ty << 2) + i) * HIDW + h * HD + (tx << 2)] = o;
    }
}

// ---------------- launch -----------------------------------------------------------
extern "C" void kernel_launch(void* const* d_in, const int* in_sizes, int n_in,
                              void* d_out, int out_size)
{
    const float* hidden = (const float*)d_in[0];
    const float* Wq  = (const float*)d_in[1];
    const float* bq  = (const float*)d_in[2];
    const float* Wk  = (const float*)d_in[3];
    const float* bk  = (const float*)d_in[4];
    const float* Wv  = (const float*)d_in[5];
    const float* bv  = (const float*)d_in[6];
    const float* dw  = (const float*)d_in[7];
    const float* pw  = (const float*)d_in[8];
    const float* sepb= (const float*)d_in[9];
    const float* Wck = (const float*)d_in[10];
    const float* bck = (const float*)d_in[11];
    const float* Wco = (const float*)d_in[12];
    const float* bco = (const float*)d_in[13];
    float* out = (float*)d_out;

    float *q, *k, *v, *dwc, *ca, *col, *ckl;
    cudaGetSymbolAddress((void**)&q,   g_q);
    cudaGetSymbolAddress((void**)&k,   g_k);
    cudaGetSymbolAddress((void**)&v,   g_v);
    cudaGetSymbolAddress((void**)&dwc, g_dwc);
    cudaGetSymbolAddress((void**)&ca,  g_ca);
    cudaGetSymbolAddress((void**)&col, g_col);
    cudaGetSymbolAddress((void**)&ckl, g_ckl);

    dim3 gg(AH / 64, TOK / 64);   // (8, 128)

    // q, k, v = hs_attn @ W^T + b
    gemm64<0><<<gg, 256>>>(hidden, HIDW, Wq, bq, nullptr, 0, q);
    gemm64<0><<<gg, 256>>>(hidden, HIDW, Wk, bk, nullptr, 0, k);
    gemm64<0><<<gg, 256>>>(hidden, HIDW, Wv, bv, nullptr, 0, v);

    // depthwise conv then pointwise GEMM with fused (* hs_conv) epilogue
    dwconv_k<<<TOK * AH / 256, 256>>>(hidden + AH, dw, dwc);
    gemm64<1><<<gg, 256>>>(dwc, AH, pw, sepb, hidden + AH, HIDW, ca);

    // ckl = softmax9(ca @ Wck^T + bck)
    ckl_gemm<<<TOK / 8, 256>>>(ca, Wck, bck, ckl);
    softmax9_k<<<TOK * NH / 256, 256>>>(ckl);

    // col = hs_conv @ Wco^T + bco ; conv_out -> out[:, 512:]
    gemm64<0><<<gg, 256>>>(hidden + AH, HIDW, Wco, bco, nullptr, 0, col);
    convout_k<<<TOK * AH / 256, 256>>>(col, ckl, out);

    // attention -> out[:, :512]
    int smem = 4 * 64 * FP * sizeof(float);
    cudaFuncSetAttribute(flash_k, cudaFuncAttributeMaxDynamicSharedMemorySize, smem);
    flash_k<<<dim3(SEQ / 64, 32), 256, smem>>>(q, k, v, out);
}

// round 5
// speedup vs baseline: 1.6744x; 1.6744x over previous
#include <cuda_runtime.h>
#include <cstdint>

#define TOK  8192      // B*S
#define AH   512       // A = H*D
#define HIDW 1024
#define SEQ  2048
#define NH   8
#define HD   64
#define KW   9

// ---------------- scratch (device globals; no allocation at launch) ----------------
__device__ float g_q  [TOK * AH];
__device__ float g_k  [TOK * AH];
__device__ float g_v  [TOK * AH];
__device__ float g_dwc[TOK * AH];
__device__ float g_ca [TOK * AH];
__device__ float g_col[TOK * AH];
__device__ float g_ckl[TOK * NH * KW];

// ---------------- fast exp on the FMA pipe ------------------------------------------
__device__ __forceinline__ float fexp(float x) {
    float y = fmaxf(x * 1.4426950408889634f, -126.0f);
    float z = y + 12582912.0f;
    int   ni = __float_as_int(z) - 0x4B400000;
    float n  = z - 12582912.0f;
    float f  = y - n;
    float p  = 1.3333558146428443e-3f;
    p = fmaf(p, f, 9.6181291976353954e-3f);
    p = fmaf(p, f, 5.5504108664821580e-2f);
    p = fmaf(p, f, 2.4022650695910071e-1f);
    p = fmaf(p, f, 6.9314718055994531e-1f);
    p = fmaf(p, f, 1.0f);
    return p * __int_as_float(0x3F800000 + (ni << 23));
}

// ---------------- tf32 helpers ------------------------------------------------------
__device__ __forceinline__ uint32_t f2tf(float f) {
    uint32_t u;
    asm("cvt.rna.tf32.f32 %0, %1;" : "=r"(u) : "f"(f));
    return u;
}

__device__ __forceinline__ void mma8(float* c, const uint32_t* a, const uint32_t* b) {
    asm volatile(
        "mma.sync.aligned.m16n8k8.row.col.f32.tf32.tf32.f32 "
        "{%0,%1,%2,%3}, {%4,%5,%6,%7}, {%8,%9}, {%0,%1,%2,%3};"
        : "+f"(c[0]), "+f"(c[1]), "+f"(c[2]), "+f"(c[3])
        : "r"(a[0]), "r"(a[1]), "r"(a[2]), "r"(a[3]), "r"(b[0]), "r"(b[1]));
}

// ---------------- tf32 tensor-core GEMM: C[m,n] = A[m,:] . W[n,:] + bias[n] ---------
// Block tile 128x128, kchunk 16, 8 warps each computing 64x32 (4x4 mma tiles of 16x8).
// EPI==1: multiply by aux[m*ldaux+n] before store.
#define APAD 20
template<int EPI>
__global__ __launch_bounds__(256) void gemm_tc(
    const float* __restrict__ A, int lda,
    const float* __restrict__ W,          // [N,512] row-major
    const float* __restrict__ bias,
    const float* __restrict__ aux, int ldaux,
    float* __restrict__ C)                // [M,512]
{
    __shared__ uint32_t As[128][APAD];
    __shared__ uint32_t Bs[128][APAD];
    const int m0 = blockIdx.y << 7;
    const int n0 = blockIdx.x << 7;
    const int t  = threadIdx.x;
    const int w  = t >> 5, lane = t & 31;
    const int q  = lane & 3, r = lane >> 2;
    const int wm = (w & 1) << 6;
    const int wn = (w >> 1) << 5;

    const int srow = t >> 2;            // 0..63
    const int skc  = (t & 3) << 2;      // 0,4,8,12
    const float* Ap = A + (size_t)(m0 + srow) * lda + skc;
    const float* Wp = W + (size_t)(n0 + srow) * AH  + skc;

    float acc[4][4][4] = {};

    float4 a0v = *(const float4*)Ap;
    float4 a1v = *(const float4*)(Ap + (size_t)64 * lda);
    float4 b0v = *(const float4*)Wp;
    float4 b1v = *(const float4*)(Wp + (size_t)64 * AH);

    for (int k0 = 0; k0 < AH; k0 += 16) {
        *(uint4*)&As[srow][skc]      = make_uint4(f2tf(a0v.x), f2tf(a0v.y), f2tf(a0v.z), f2tf(a0v.w));
        *(uint4*)&As[srow + 64][skc] = make_uint4(f2tf(a1v.x), f2tf(a1v.y), f2tf(a1v.z), f2tf(a1v.w));
        *(uint4*)&Bs[srow][skc]      = make_uint4(f2tf(b0v.x), f2tf(b0v.y), f2tf(b0v.z), f2tf(b0v.w));
        *(uint4*)&Bs[srow + 64][skc] = make_uint4(f2tf(b1v.x), f2tf(b1v.y), f2tf(b1v.z), f2tf(b1v.w));
        __syncthreads();
        if (k0 + 16 < AH) {
            a0v = *(const float4*)(Ap + k0 + 16);
            a1v = *(const float4*)(Ap + (size_t)64 * lda + k0 + 16);
            b0v = *(const float4*)(Wp + k0 + 16);
            b1v = *(const float4*)(Wp + (size_t)64 * AH + k0 + 16);
        }
        #pragma unroll
        for (int ks = 0; ks < 2; ks++) {
            const int kb = ks << 3;
            uint32_t af[4][4], bf[4][2];
            #pragma unroll
            for (int mt = 0; mt < 4; mt++) {
                int m = wm + (mt << 4) + r;
                af[mt][0] = As[m][kb + q];
                af[mt][1] = As[m + 8][kb + q];
                af[mt][2] = As[m][kb + q + 4];
                af[mt][3] = As[m + 8][kb + q + 4];
            }
            #pragma unroll
            for (int nt = 0; nt < 4; nt++) {
                int n = wn + (nt << 3) + r;
                bf[nt][0] = Bs[n][kb + q];
                bf[nt][1] = Bs[n][kb + q + 4];
            }
            #pragma unroll
            for (int mt = 0; mt < 4; mt++)
                #pragma unroll
                for (int nt = 0; nt < 4; nt++)
                    mma8(acc[mt][nt], af[mt], bf[nt]);
        }
        __syncthreads();
    }

    #pragma unroll
    for (int mt = 0; mt < 4; mt++) {
        int mr0 = m0 + wm + (mt << 4) + r;
        #pragma unroll
        for (int nt = 0; nt < 4; nt++) {
            int n = n0 + wn + (nt << 3) + (q << 1);
            float bb0 = bias[n], bb1 = bias[n + 1];
            float v0 = acc[mt][nt][0] + bb0;
            float v1 = acc[mt][nt][1] + bb1;
            float v2 = acc[mt][nt][2] + bb0;
            float v3 = acc[mt][nt][3] + bb1;
            if (EPI == 1) {
                float2 x0 = *(const float2*)&aux[(size_t)mr0 * ldaux + n];
                float2 x1 = *(const float2*)&aux[(size_t)(mr0 + 8) * ldaux + n];
                v0 *= x0.x; v1 *= x0.y; v2 *= x1.x; v3 *= x1.y;
            }
            *(float2*)&C[(size_t)mr0 * AH + n]       = make_float2(v0, v1);
            *(float2*)&C[(size_t)(mr0 + 8) * AH + n] = make_float2(v2, v3);
        }
    }
}

// ---------------- depthwise 9-tap conv along sequence -------------------------------
__global__ void dwconv_k(const float* __restrict__ hc, const float* __restrict__ dw,
                         float* __restrict__ o)
{
    int idx = blockIdx.x * 256 + threadIdx.x;
    int tok = idx >> 9, c = idx & 511;
    int s = tok & (SEQ - 1);
    float acc = 0.f;
    #pragma unroll
    for (int k = 0; k < KW; k++) {
        int sp = s + k - 4;
        if ((unsigned)sp < (unsigned)SEQ)
            acc = fmaf(hc[(size_t)(tok + k - 4) * HIDW + c], dw[c * KW + k], acc);
    }
    o[idx] = acc;
}

// ---------------- ckl GEMM: [8192,72] = ca @ Wck^T + bck ----------------------------
__global__ __launch_bounds__(256) void ckl_gemm(
    const float* __restrict__ ca, const float* __restrict__ Wck,
    const float* __restrict__ bck, float* __restrict__ ckl)
{
    __shared__ float sca[8][AH];
    int tok0 = blockIdx.x << 3;
    for (int e = threadIdx.x; e < 8 * AH; e += 256)
        sca[e >> 9][e & 511] = ca[((size_t)tok0 << 9) + e];
    __syncthreads();
    int w = threadIdx.x >> 5, lane = threadIdx.x & 31;
    const float* srow = sca[w];
    for (int n = lane; n < NH * KW; n += 32) {
        const float* wr = Wck + (size_t)n * AH;
        float a0 = 0.f, a1 = 0.f, a2 = 0.f, a3 = 0.f;
        #pragma unroll 4
        for (int cc = 0; cc < AH; cc += 4) {
            a0 = fmaf(srow[cc + 0], wr[cc + 0], a0);
            a1 = fmaf(srow[cc + 1], wr[cc + 1], a1);
            a2 = fmaf(srow[cc + 2], wr[cc + 2], a2);
            a3 = fmaf(srow[cc + 3], wr[cc + 3], a3);
        }
        ckl[(size_t)(tok0 + w) * (NH * KW) + n] = a0 + a1 + a2 + a3 + bck[n];
    }
}

// ---------------- softmax over K=9 groups -------------------------------------------
__global__ void softmax9_k(float* __restrict__ ckl)
{
    int id = blockIdx.x * 256 + threadIdx.x;
    float* p = ckl + (size_t)id * KW;
    float v[KW];
    float mx = -1e30f;
    #pragma unroll
    for (int k = 0; k < KW; k++) { v[k] = p[k]; mx = fmaxf(mx, v[k]); }
    float s = 0.f;
    #pragma unroll
    for (int k = 0; k < KW; k++) { v[k] = fexp(v[k] - mx); s += v[k]; }
    float inv = 1.f / s;
    #pragma unroll
    for (int k = 0; k < KW; k++) p[k] = v[k] * inv;
}

// ---------------- conv_out ----------------------------------------------------------
__global__ void convout_k(const float* __restrict__ col, const float* __restrict__ ckl,
                          float* __restrict__ out)
{
    int idx = blockIdx.x * 256 + threadIdx.x;
    int tok = idx >> 9, c = idx & 511;
    int s = tok & (SEQ - 1);
    int h = c >> 6;
    const float* cw = ckl + (size_t)tok * (NH * KW) + h * KW;
    float acc = 0.f;
    #pragma unroll
    for (int k = 0; k < KW; k++) {
        int sp = s + k - 4;
        if ((unsigned)sp < (unsigned)SEQ)
            acc = fmaf(col[(size_t)(tok + k - 4) * AH + c], cw[k], acc);
    }
    out[(size_t)tok * HIDW + AH + c] = acc;
}

// ---------------- flash attention, tf32 tensor cores --------------------------------
// 128 q-rows per block (8 warps x 16 rows), 64-key tiles, D=64.
#define KPAD 68   // Ks[key][d] pad: B-frag rows indexed by lane/4 -> conflict-free
#define VPAD 72   // Vs[key][d] pad: B-frag rows indexed by lane%4 -> conflict-free
#define PPAD 76   // Ps[row][key] pad: A-frag rows (lane/4, +8) -> conflict-free
__global__ __launch_bounds__(256) void flash_tc(
    const float* __restrict__ Q, const float* __restrict__ Kd,
    const float* __restrict__ V, float* __restrict__ out)
{
    extern __shared__ uint32_t sh[];
    uint32_t* Ks = sh;                       // [64][KPAD]
    uint32_t* Vs = sh + 64 * KPAD;           // [64][VPAD]
    uint32_t* Ps = sh + 64 * KPAD + 64 * VPAD;  // [128][PPAD]

    const int bh = blockIdx.y;
    const int b = bh >> 3, h = bh & 7;
    const int q0 = blockIdx.x << 7;
    const int t = threadIdx.x;
    const int w = t >> 5, lane = t & 31;
    const int q = lane & 3, r = lane >> 2;
    const size_t base = (size_t)b * SEQ * AH + h * HD;

    // Q fragments held in registers for the whole kernel (scale folded in)
    uint32_t qa[8][4];
    {
        const float* Q0 = Q + base + (size_t)(q0 + w * 16 + r) * AH;
        const float* Q1 = Q0 + 8 * AH;
        #pragma unroll
        for (int tk = 0; tk < 8; tk++) {
            int d = (tk << 3) + q;
            qa[tk][0] = f2tf(Q0[d] * 0.125f);
            qa[tk][1] = f2tf(Q1[d] * 0.125f);
            qa[tk][2] = f2tf(Q0[d + 4] * 0.125f);
            qa[tk][3] = f2tf(Q1[d + 4] * 0.125f);
        }
    }

    float o[8][4] = {};
    float m0r = -1e30f, m1r = -1e30f, l0 = 0.f, l1 = 0.f;

    for (int kt = 0; kt < SEQ; kt += 64) {
        // load K,V tiles (natural [key][d] layout, uint4 stores)
        #pragma unroll
        for (int j = 0; j < 4; j++) {
            int fv = t + (j << 8);            // 1024 float4s
            int key = fv >> 4, d = (fv & 15) << 2;
            float4 kv = *(const float4*)(Kd + base + (size_t)(kt + key) * AH + d);
            float4 vv = *(const float4*)(V  + base + (size_t)(kt + key) * AH + d);
            *(uint4*)&Ks[key * KPAD + d] = make_uint4(f2tf(kv.x), f2tf(kv.y), f2tf(kv.z), f2tf(kv.w));
            *(uint4*)&Vs[key * VPAD + d] = make_uint4(f2tf(vv.x), f2tf(vv.y), f2tf(vv.z), f2tf(vv.w));
        }
        __syncthreads();

        // S = Q K^T  (B = K^T: b0 = K[key=n][d=k])
        float s[8][4] = {};
        #pragma unroll
        for (int tk = 0; tk < 8; tk++) {
            #pragma unroll
            for (int nt = 0; nt < 8; nt++) {
                uint32_t bf[2];
                bf[0] = Ks[((nt << 3) + r) * KPAD + (tk << 3) + q];
                bf[1] = Ks[((nt << 3) + r) * KPAD + (tk << 3) + q + 4];
                mma8(s[nt], qa[tk], bf);
            }
        }

        // online softmax: thread owns rows (lane/4) and (lane/4+8)
        float rm0 = -1e30f, rm1 = -1e30f;
        #pragma unroll
        for (int nt = 0; nt < 8; nt++) {
            rm0 = fmaxf(rm0, fmaxf(s[nt][0], s[nt][1]));
            rm1 = fmaxf(rm1, fmaxf(s[nt][2], s[nt][3]));
        }
        rm0 = fmaxf(rm0, __shfl_xor_sync(0xffffffffu, rm0, 1));
        rm0 = fmaxf(rm0, __shfl_xor_sync(0xffffffffu, rm0, 2));
        rm1 = fmaxf(rm1, __shfl_xor_sync(0xffffffffu, rm1, 1));
        rm1 = fmaxf(rm1, __shfl_xor_sync(0xffffffffu, rm1, 2));
        float mn0 = fmaxf(m0r, rm0), mn1 = fmaxf(m1r, rm1);
        float c0 = fexp(m0r - mn0), c1 = fexp(m1r - mn1);
        m0r = mn0; m1r = mn1;

        float rs0 = 0.f, rs1 = 0.f;
        uint32_t* Pw = Ps + (w * 16 + r) * PPAD;
        #pragma unroll
        for (int nt = 0; nt < 8; nt++) {
            float p0 = fexp(s[nt][0] - mn0);
            float p1 = fexp(s[nt][1] - mn0);
            float p2 = fexp(s[nt][2] - mn1);
            float p3 = fexp(s[nt][3] - mn1);
            rs0 += p0 + p1; rs1 += p2 + p3;
            int col = (nt << 3) + (q << 1);
            *(uint2*)&Pw[col]            = make_uint2(f2tf(p0), f2tf(p1));
            *(uint2*)&Pw[8 * PPAD + col] = make_uint2(f2tf(p2), f2tf(p3));
        }
        rs0 += __shfl_xor_sync(0xffffffffu, rs0, 1);
        rs0 += __shfl_xor_sync(0xffffffffu, rs0, 2);
        rs1 += __shfl_xor_sync(0xffffffffu, rs1, 1);
        rs1 += __shfl_xor_sync(0xffffffffu, rs1, 2);
        l0 = l0 * c0 + rs0;
        l1 = l1 * c1 + rs1;
        #pragma unroll
        for (int nt = 0; nt < 8; nt++) {
            o[nt][0] *= c0; o[nt][1] *= c0; o[nt][2] *= c1; o[nt][3] *= c1;
        }
        __syncwarp();

        // O += P V
        const uint32_t* Pr = Ps + (w * 16) * PPAD;
        #pragma unroll
        for (int tk = 0; tk < 8; tk++) {
            uint32_t af[4];
            af[0] = Pr[r * PPAD + (tk << 3) + q];
            af[1] = Pr[(r + 8) * PPAD + (tk << 3) + q];
            af[2] = Pr[r * PPAD + (tk << 3) + q + 4];
            af[3] = Pr[(r + 8) * PPAD + (tk << 3) + q + 4];
            #pragma unroll
            for (int nt = 0; nt < 8; nt++) {
                uint32_t bf[2];
                bf[0] = Vs[((tk << 3) + q) * VPAD + (nt << 3) + r];
                bf[1] = Vs[((tk << 3) + q + 4) * VPAD + (nt << 3) + r];
                mma8(o[nt], af, bf);
            }
        }
        __syncthreads();
    }

    float inv0 = 1.f / l0, inv1 = 1.f / l1;
    int row0 = b * SEQ + q0 + w * 16 + r;
    #pragma unroll
    for (int nt = 0; nt < 8; nt++) {
        int col = h * HD + (nt << 3) + (q << 1);
        *(float2*)&out[(size_t)row0 * HIDW + col]       = make_float2(o[nt][0] * inv0, o[nt][1] * inv0);
        *(float2*)&out[(size_t)(row0 + 8) * HIDW + col] = make_float2(o[nt][2] * inv1, o[nt][3] * inv1);
    }
}

// ---------------- launch -------------------------------------------------------------
extern "C" void kernel_launch(void* const* d_in, const int* in_sizes, int n_in,
                              void* d_out, int out_size)
{
    const float* hidden = (const float*)d_in[0];
    const float* Wq  = (const float*)d_in[1];
    const float* bq  = (const float*)d_in[2];
    const float* Wk  = (const float*)d_in[3];
    const float* bk  = (const float*)d_in[4];
    const float* Wv  = (const float*)d_in[5];
    const float* bv  = (const float*)d_in[6];
    const float* dw  = (const float*)d_in[7];
    const float* pw  = (const float*)d_in[8];
    const float* sepb= (const float*)d_in[9];
    const float* Wck = (const float*)d_in[10];
    const float* bck = (const float*)d_in[11];
    const float* Wco = (const float*)d_in[12];
    const float* bco = (const float*)d_in[13];
    float* out = (float*)d_out;

    float *q, *k, *v, *dwc, *ca, *col, *ckl;
    cudaGetSymbolAddress((void**)&q,   g_q);
    cudaGetSymbolAddress((void**)&k,   g_k);
    cudaGetSymbolAddress((void**)&v,   g_v);
    cudaGetSymbolAddress((void**)&dwc, g_dwc);
    cudaGetSymbolAddress((void**)&ca,  g_ca);
    cudaGetSymbolAddress((void**)&col, g_col);
    cudaGetSymbolAddress((void**)&ckl, g_ckl);

    dim3 gg(AH / 128, TOK / 128);   // (4, 64)

    gemm_tc<0><<<gg, 256>>>(hidden, HIDW, Wq, bq, nullptr, 0, q);
    gemm_tc<0><<<gg, 256>>>(hidden, HIDW, Wk, bk, nullptr, 0, k);
    gemm_tc<0><<<gg, 256>>>(hidden, HIDW, Wv, bv, nullptr, 0, v);

    dwconv_k<<<TOK * AH / 256, 256>>>(hidden + AH, dw, dwc);
    gemm_tc<1><<<gg, 256>>>(dwc, AH, pw, sepb, hidden + AH, HIDW, ca);

    ckl_gemm<<<TOK / 8, 256>>>(ca, Wck, bck, ckl);
    softmax9_k<<<TOK * NH / 256, 256>>>(ckl);

    gemm_tc<0><<<gg, 256>>>(hidden + AH, HIDW, Wco, bco, nullptr, 0, col);
    convout_k<<<TOK * AH / 256, 256>>>(col, ckl, out);

    int smem = (64 * KPAD + 64 * VPAD + 128 * PPAD) * 4;
    cudaFuncSetAttribute(flash_tc, cudaFuncAttributeMaxDynamicSharedMemorySize, smem);
    flash_tc<<<dim3(SEQ / 128, 32), 256, smem>>>(q, k, v, out);
}